// round 11
// baseline (speedup 1.0000x reference)
#include <cuda_runtime.h>
#include <cuda_fp16.h>
#include <cuda_bf16.h>
#include <mma.h>
#include <cstdint>

using namespace nvcuda;

// ================= problem constants =================
constexpr int K_DIM = 1024;
constexpr int N_DIM = 4096;
constexpr int M_DIM = 32768;

constexpr int MT = 128;               // CTA tile M
constexpr int NT = 256;               // CTA tile N
constexpr int KT = 32;                // CTA tile K per stage
constexpr int STAGES = 5;
constexpr int NKT = K_DIM / KT;       // 32 k-iterations

constexpr int AROWB = 80;             // smem row stride bytes (40 halves): 64B data + 16B pad
constexpr int LDH = AROWB / 2;        // 40 halves leading dim
constexpr int A_STAGE_B = MT * AROWB; // 10240
constexpr int B_STAGE_B = NT * AROWB; // 20480
constexpr int STAGE_B = A_STAGE_B + B_STAGE_B;       // 30720
constexpr int SMEM_BIAS_B = 1024;
constexpr int SMEM_TOTAL = SMEM_BIAS_B + STAGES * STAGE_B;  // 154624

// ============ device scratch (__device__ globals; no allocs allowed) ============
__device__ __align__(128) __half g_xa[(size_t)M_DIM * K_DIM];  // BF15(x) as fp16, [M][K]
__device__ __align__(128) __half g_wh[(size_t)N_DIM * K_DIM];  // fp16(W), [N][K]

// ================= helpers =================
__device__ __forceinline__ uint32_t smem_u32(const void* p) {
    uint32_t a;
    asm("{ .reg .u64 t; cvta.to.shared.u64 t, %1; cvt.u32.u64 %0, t; }" : "=r"(a) : "l"(p));
    return a;
}
__device__ __forceinline__ void cp_async16(uint32_t s, const void* g) {
    asm volatile("cp.async.cg.shared.global [%0], [%1], 16;" :: "r"(s), "l"(g));
}

// ================= conversion kernels =================
// x fp32 -> BF15 (clear low 17 mantissa bits == reference's truncation; fp32 is
// sign-magnitude) -> fp16 (exact: 6-bit mantissa fits fp16's 10).
__global__ void conv_x_kernel(const float* __restrict__ x) {
    size_t i = ((size_t)blockIdx.x * blockDim.x + threadIdx.x) * 8;
    float4 f0 = *(const float4*)(x + i);
    float4 f1 = *(const float4*)(x + i + 4);
    auto bf15 = [](float v) { return __uint_as_float(__float_as_uint(v) & 0xFFFE0000u); };
    __half2 h[4];
    h[0] = __floats2half2_rn(bf15(f0.x), bf15(f0.y));
    h[1] = __floats2half2_rn(bf15(f0.z), bf15(f0.w));
    h[2] = __floats2half2_rn(bf15(f1.x), bf15(f1.y));
    h[3] = __floats2half2_rn(bf15(f1.z), bf15(f1.w));
    *(uint4*)(g_xa + i) = *(uint4*)h;
}

// W fp32 -> fp16 (rn): output rms rel err ~2.8e-4, well under 1e-3.
__global__ void conv_w_kernel(const float* __restrict__ w) {
    size_t i = ((size_t)blockIdx.x * blockDim.x + threadIdx.x) * 8;
    float4 f0 = *(const float4*)(w + i);
    float4 f1 = *(const float4*)(w + i + 4);
    __half2 h[4];
    h[0] = __floats2half2_rn(f0.x, f0.y);
    h[1] = __floats2half2_rn(f0.z, f0.w);
    h[2] = __floats2half2_rn(f1.x, f1.y);
    h[3] = __floats2half2_rn(f1.z, f1.w);
    *(uint4*)(g_wh + i) = *(uint4*)h;
}

// ================= GEMM kernel (wmma, 5-stage cp.async pipeline) =================
__global__ __launch_bounds__(256, 1)
void gemm_kernel(const float* __restrict__ bias, float* __restrict__ out) {
    extern __shared__ char smem[];
    float* biasS = (float*)smem;
    char* stageC = smem + SMEM_BIAS_B;
    const uint32_t sb = smem_u32(smem) + SMEM_BIAS_B;

    const int tid = threadIdx.x, lane = tid & 31, warp = tid >> 5;
    const int wm = warp >> 2, wn = warp & 3;         // 2 x 4 warp grid, 64x64 warp tile
    const int ntile = blockIdx.x, mtile = blockIdx.y;

    biasS[tid] = bias[ntile * NT + tid];             // 256 threads == NT

    const __half* gA = g_xa + (size_t)mtile * MT * K_DIM;
    const __half* gB = g_wh + (size_t)ntile * NT * K_DIM;

    auto load_stage = [&](int slot, int kt) {
        const int k0 = kt * KT;
        const uint32_t sA = sb + slot * STAGE_B;
        const uint32_t sB = sA + A_STAGE_B;
#pragma unroll
        for (int it = 0; it < 2; it++) {             // A: 128 rows * 4 chunks = 512
            int idx = tid + it * 256;
            int r = idx >> 2, c = idx & 3;
            cp_async16(sA + r * AROWB + c * 16, gA + (size_t)r * K_DIM + k0 + c * 8);
        }
#pragma unroll
        for (int it = 0; it < 4; it++) {             // B: 256 rows * 4 chunks = 1024
            int idx = tid + it * 256;
            int r = idx >> 2, c = idx & 3;
            cp_async16(sB + r * AROWB + c * 16, gB + (size_t)r * K_DIM + k0 + c * 8);
        }
        asm volatile("cp.async.commit_group;" ::: "memory");
    };

#pragma unroll
    for (int s = 0; s < STAGES - 1; s++) load_stage(s, s);

    wmma::fragment<wmma::accumulator, 16, 16, 16, float> acc[4][4];
#pragma unroll
    for (int i = 0; i < 4; i++)
#pragma unroll
        for (int j = 0; j < 4; j++) wmma::fill_fragment(acc[i][j], 0.0f);

    for (int kt = 0; kt < NKT; kt++) {
        const int slot = kt % STAGES;
        asm volatile("cp.async.wait_group %0;" :: "n"(STAGES - 2));
        __syncthreads();

        // Issue next stage first (its slot was consumed at kt-1; all warps past
        // that via the syncthreads). Tail iterations commit an EMPTY group so
        // wait_group's "all but newest 3" always covers stage kt.
        const int nk = kt + STAGES - 1;
        if (nk < NKT) load_stage(nk % STAGES, nk);
        else asm volatile("cp.async.commit_group;" ::: "memory");

        const __half* hA = (const __half*)(stageC + slot * STAGE_B);
        const __half* hB = (const __half*)(stageC + slot * STAGE_B + A_STAGE_B);
#pragma unroll
        for (int k16 = 0; k16 < 2; k16++) {
            wmma::fragment<wmma::matrix_a, 16, 16, 16, __half, wmma::row_major> fa[4];
            wmma::fragment<wmma::matrix_b, 16, 16, 16, __half, wmma::col_major> fb[4];
#pragma unroll
            for (int i = 0; i < 4; i++)
                wmma::load_matrix_sync(fa[i], hA + (wm * 64 + i * 16) * LDH + k16 * 16, LDH);
#pragma unroll
            for (int j = 0; j < 4; j++)
                wmma::load_matrix_sync(fb[j], hB + (wn * 64 + j * 16) * LDH + k16 * 16, LDH);
#pragma unroll
            for (int i = 0; i < 4; i++)
#pragma unroll
                for (int j = 0; j < 4; j++)
                    wmma::mma_sync(acc[i][j], fa[i], fb[j], acc[i][j]);
        }
    }

    // -------- epilogue: smem staging, bias + double rounding, FP32 output --------
    // Output buffer is fp32 (__output__ dtype): write float(bf16(float(bf16(acc)) + bias)).
    __syncthreads();                                  // all warps done reading stages
    float* reg = (float*)stageC + warp * 1024;        // 16x64 fp32 per warp (4KB)
    const int h = lane >> 4, q = lane & 15;
#pragma unroll
    for (int i = 0; i < 4; i++) {
#pragma unroll
        for (int j = 0; j < 4; j++)
            wmma::store_matrix_sync(reg + j * 16, acc[i][j], 64, wmma::mem_row_major);
        __syncwarp();
        size_t mbase = (size_t)mtile * MT + wm * 64 + i * 16;
        size_t nbase = (size_t)ntile * NT + wn * 64;
#pragma unroll
        for (int s = 0; s < 8; s++) {
            int r = 2 * s + h;
            float4 v = *(float4*)(reg + r * 64 + q * 4);
            float b0 = biasS[wn * 64 + q * 4 + 0];
            float b1 = biasS[wn * 64 + q * 4 + 1];
            float b2 = biasS[wn * 64 + q * 4 + 2];
            float b3 = biasS[wn * 64 + q * 4 + 3];
            // reference double rounding: bf16(acc) -> fp32 +bias -> bf16 -> (as fp32)
            float4 o;
            o.x = __bfloat162float(__float2bfloat16_rn(__bfloat162float(__float2bfloat16_rn(v.x)) + b0));
            o.y = __bfloat162float(__float2bfloat16_rn(__bfloat162float(__float2bfloat16_rn(v.y)) + b1));
            o.z = __bfloat162float(__float2bfloat16_rn(__bfloat162float(__float2bfloat16_rn(v.z)) + b2));
            o.w = __bfloat162float(__float2bfloat16_rn(__bfloat162float(__float2bfloat16_rn(v.w)) + b3));
            *(float4*)(out + (mbase + r) * N_DIM + nbase + q * 4) = o;
        }
        __syncwarp();                                 // reads done before next store
    }
}

// ================= launch =================
extern "C" void kernel_launch(void* const* d_in, const int* in_sizes, int n_in,
                              void* d_out, int out_size) {
    // Resolve inputs BY ELEMENT COUNT (ordering-proof):
    //   x: 134217728, weight: 4194304, bias: 4096.
    const float* x = nullptr;
    const float* w = nullptr;
    const float* bias = nullptr;
    for (int i = 0; i < n_in; i++) {
        if (in_sizes[i] == M_DIM * K_DIM) x = (const float*)d_in[i];
        else if (in_sizes[i] == N_DIM * K_DIM) w = (const float*)d_in[i];
        else if (in_sizes[i] == N_DIM) bias = (const float*)d_in[i];
    }
    float* out = (float*)d_out;   // fp32 output buffer

    cudaFuncSetAttribute(gemm_kernel, cudaFuncAttributeMaxDynamicSharedMemorySize, SMEM_TOTAL);

    conv_x_kernel<<<(int)((size_t)M_DIM * K_DIM / 2048), 256>>>(x);
    conv_w_kernel<<<(int)((size_t)N_DIM * K_DIM / 2048), 256>>>(w);
    gemm_kernel<<<dim3(N_DIM / NT, M_DIM / MT), 256, SMEM_TOTAL>>>(bias, out);
}